// round 1
// baseline (speedup 1.0000x reference)
#include <cuda_runtime.h>
#include <cuda_bf16.h>
#include <math.h>

// Problem constants
#define IN_CH   4
#define OUT_CH  8
#define KW      8
#define N_LAYERS 2
#define N_IN    32
#define N_QUBITS 7
#define QDIM    128
#define BATCH   16
#define LIN     2048
#define LOUT    (LIN - KW + 1)   // 2041

// Scratch (device globals — no allocation allowed)
__device__ float2 g_C[OUT_CH * N_IN * QDIM];   // circuit columns: [o][j][m]
__device__ float  g_A[OUT_CH * N_IN * N_IN];   // quadratic-form matrices [o][i][j]

// ---------------------------------------------------------------------------
// Kernel 1: simulate circuit on each basis vector e_j, per out-channel.
// One warp per (o, j). 128 complex amps = 4 per lane: m = lane + 32*r.
// Gate for (layer l, qubit q) acts on bit p = 6 - q of m.
//   p in {5,6}: within-thread (bits of r). p in {0..4}: cross-lane shuffle.
// ---------------------------------------------------------------------------
__global__ __launch_bounds__(1024, 1)
void sim_kernel(const float* __restrict__ thetas) {
    const int warp = threadIdx.x >> 5;     // 0..31  -> column j
    const int lane = threadIdx.x & 31;
    const int o = blockIdx.x;              // 0..7
    const int j = warp;

    float re[4], im[4];
#pragma unroll
    for (int r = 0; r < 4; r++) { re[r] = 0.f; im[r] = 0.f; }
    if (lane == j) re[0] = 1.0f;           // e_j: m=j (<32) -> r=0, lane=j

    for (int l = 0; l < N_LAYERS; l++) {
        for (int q = 0; q < N_QUBITS; q++) {
            const float* th = thetas + (((o * N_LAYERS) + l) * N_QUBITS + q) * 3;
            float a = th[0], b = th[1], g = th[2];
            float cb = cosf(0.5f * b), sb = sinf(0.5f * b);
            float sp, cp; sincosf(0.5f * (a + g), &sp, &cp);  // ep = cp + i sp
            float sm, cm; sincosf(0.5f * (a - g), &sm, &cm);  // em = cm + i sm
            // u00 = conj(ep)*cb, u01 = -conj(em)*sb, u10 = em*sb, u11 = ep*cb
            float u00r =  cp * cb, u00i = -sp * cb;
            float u01r = -cm * sb, u01i =  sm * sb;
            float u10r =  cm * sb, u10i =  sm * sb;
            float u11r =  cp * cb, u11i =  sp * cb;

            int p = 6 - q;   // bit of m this gate acts on
            if (p >= 5) {
                int d = 1 << (p - 5);   // bit of r
#pragma unroll
                for (int r0 = 0; r0 < 4; r0++) {
                    if (r0 & d) continue;
                    int r1 = r0 | d;
                    float a0r = re[r0], a0i = im[r0];
                    float a1r = re[r1], a1i = im[r1];
                    re[r0] = u00r*a0r - u00i*a0i + u01r*a1r - u01i*a1i;
                    im[r0] = u00r*a0i + u00i*a0r + u01r*a1i + u01i*a1r;
                    re[r1] = u10r*a0r - u10i*a0i + u11r*a1r - u11i*a1i;
                    im[r1] = u10r*a0i + u10i*a0r + u11r*a1i + u11i*a1r;
                }
            } else {
                int mask = 1 << p;
                int bit = (lane >> p) & 1;
#pragma unroll
                for (int r = 0; r < 4; r++) {
                    float otr = __shfl_xor_sync(0xffffffffu, re[r], mask);
                    float oti = __shfl_xor_sync(0xffffffffu, im[r], mask);
                    float sr = re[r], si = im[r];
                    if (bit == 0) {
                        // own = a0, other = a1
                        re[r] = u00r*sr - u00i*si + u01r*otr - u01i*oti;
                        im[r] = u00r*si + u00i*sr + u01r*oti + u01i*otr;
                    } else {
                        // own = a1, other = a0
                        re[r] = u10r*otr - u10i*oti + u11r*sr - u11i*si;
                        im[r] = u10r*oti + u10i*otr + u11r*si + u11i*sr;
                    }
                }
            }
        }
        // entangling diagonal: sign = (-1)^(C(popc(m),2))
#pragma unroll
        for (int r = 0; r < 4; r++) {
            int m = lane + 32 * r;
            int k = __popc(m);
            if (((k * (k - 1)) >> 1) & 1) { re[r] = -re[r]; im[r] = -im[r]; }
        }
    }

#pragma unroll
    for (int r = 0; r < 4; r++) {
        int m = lane + 32 * r;
        g_C[(o * N_IN + j) * QDIM + m] = make_float2(re[r], im[r]);
    }
}

// ---------------------------------------------------------------------------
// Kernel 2: A_o[i][j] = sum_m z0(m) * (Ci[m].Cj[m] real inner product)
// z0(m) = +1 for m<64, -1 otherwise.
// One block per o; C transposed in shared as sC[m][col] to avoid conflicts.
// ---------------------------------------------------------------------------
__global__ __launch_bounds__(256, 1)
void gram_kernel() {
    __shared__ float2 sC[QDIM * N_IN];    // [m][col], 32 KB
    const int o = blockIdx.x;
    for (int idx = threadIdx.x; idx < N_IN * QDIM; idx += 256) {
        int col = idx / QDIM, m = idx % QDIM;
        sC[m * N_IN + col] = g_C[o * N_IN * QDIM + idx];
    }
    __syncthreads();
    for (int e = threadIdx.x; e < N_IN * N_IN; e += 256) {
        int i = e >> 5, j = e & 31;
        float s = 0.f;
#pragma unroll 4
        for (int m = 0; m < QDIM; m++) {
            float2 ci = sC[m * N_IN + i];
            float2 cj = sC[m * N_IN + j];
            float v = ci.x * cj.x + ci.y * cj.y;
            s += (m < 64) ? v : -v;
        }
        g_A[o * N_IN * N_IN + e] = s;
    }
}

// ---------------------------------------------------------------------------
// Kernel 3: main conv. Each thread owns one output position t:
//   out[b][o][t] = (w^T A_o w) / (w^T w),  w[c*8+k] = x[b][c][t+k]
// ---------------------------------------------------------------------------
#define TILE_T 128

__global__ __launch_bounds__(TILE_T, 8)
void conv_kernel(const float* __restrict__ x, float* __restrict__ out) {
    __shared__ float sA[OUT_CH * N_IN * N_IN];        // 32 KB
    __shared__ float xs[IN_CH][TILE_T + KW];          // tile + halo

    const int b = blockIdx.y;
    const int t0 = blockIdx.x * TILE_T;
    const int tid = threadIdx.x;

    for (int idx = tid; idx < OUT_CH * N_IN * N_IN; idx += TILE_T)
        sA[idx] = g_A[idx];
    for (int idx = tid; idx < IN_CH * (TILE_T + KW); idx += TILE_T) {
        int c = idx / (TILE_T + KW), i = idx % (TILE_T + KW);
        int gi = t0 + i;
        xs[c][i] = (gi < LIN) ? x[(b * IN_CH + c) * LIN + gi] : 0.f;
    }
    __syncthreads();

    const int t = t0 + tid;
    if (t >= LOUT) return;

    float w[N_IN];
    float n2 = 0.f;
#pragma unroll
    for (int c = 0; c < IN_CH; c++)
#pragma unroll
        for (int k = 0; k < KW; k++) {
            float v = xs[c][tid + k];
            w[c * KW + k] = v;
            n2 += v * v;
        }
    const float inv = 1.0f / n2;

#pragma unroll 1
    for (int o = 0; o < OUT_CH; o++) {
        float acc = 0.f;
        const float4* Ao = reinterpret_cast<const float4*>(&sA[o * N_IN * N_IN]);
#pragma unroll 4
        for (int i = 0; i < N_IN; i++) {
            const float4* row = Ao + i * (N_IN / 4);
            float s = 0.f;
#pragma unroll
            for (int j4 = 0; j4 < N_IN / 4; j4++) {
                float4 a4 = row[j4];
                s += a4.x * w[4 * j4 + 0] + a4.y * w[4 * j4 + 1]
                   + a4.z * w[4 * j4 + 2] + a4.w * w[4 * j4 + 3];
            }
            acc += s * w[i];
        }
        out[(b * OUT_CH + o) * LOUT + t] = acc * inv;
    }
}

// ---------------------------------------------------------------------------
extern "C" void kernel_launch(void* const* d_in, const int* in_sizes, int n_in,
                              void* d_out, int out_size) {
    const float* x      = (const float*)d_in[0];   // (16, 4, 2048) f32
    const float* thetas = (const float*)d_in[1];   // (8, 2, 7, 3) f32
    float* out = (float*)d_out;                    // (16, 8, 2041) f32

    sim_kernel<<<OUT_CH, 1024>>>(thetas);
    gram_kernel<<<OUT_CH, 256>>>();
    dim3 grid((LOUT + TILE_T - 1) / TILE_T, BATCH);
    conv_kernel<<<grid, TILE_T>>>(x, out);
}

// round 2
// speedup vs baseline: 1.7769x; 1.7769x over previous
#include <cuda_runtime.h>
#include <cuda_bf16.h>
#include <math.h>

#define IN_CH    4
#define OUT_CH   8
#define KW       8
#define N_LAYERS 2
#define N_IN     32
#define N_QUBITS 7
#define QDIM     128
#define BATCH    16
#define LIN      2048
#define LOUT     (LIN - KW + 1)   // 2041
#define NGATES   (N_LAYERS * N_QUBITS)

// Quadratic-form matrices, symmetric-packed: B[o][i][j] = 0 (j<i), A_ii (j==i), 2*A_ij (j>i)
__device__ float g_B[OUT_CH * N_IN * N_IN];

// ---------------------------------------------------------------------------
// Kernel 1 (fused): simulate circuit on all 32 basis vectors for one out-channel,
// then reduce to the 32x32 quadratic-form matrix B_o. One block per o.
//   - 14 gate matrices computed ONCE per block (threads 0..13) with fast trig.
//   - warp j simulates e_j: 128 amps, 4/lane (m = lane + 32*r); gate q acts on
//     bit p = 6-q (p>=5 in-thread over r, p<5 via shfl_xor).
//   - columns stored in shared with stride-33 padding (conflict-free both ways).
//   - phase C: thread e=(i,j) computes A_ij = sum_m z0(m)*(Re·Re+Im·Im).
// ---------------------------------------------------------------------------
__global__ __launch_bounds__(1024, 1)
void build_kernel(const float* __restrict__ thetas) {
    __shared__ float sU[NGATES][8];          // per-gate 2x2 complex matrix
    __shared__ float sCr[QDIM * 33];         // [m][j] real, padded
    __shared__ float sCi[QDIM * 33];         // [m][j] imag, padded

    const int o = blockIdx.x;
    const int tid = threadIdx.x;
    const int warp = tid >> 5;               // column j
    const int lane = tid & 31;

    // Phase A: gate matrices (fast intrinsics; error ~1e-6, threshold 1e-3)
    if (tid < NGATES) {
        const float* th = thetas + (o * NGATES + tid) * 3;
        float a = th[0], b = th[1], g = th[2];
        float sb, cb; __sincosf(0.5f * b, &sb, &cb);
        float sp, cp; __sincosf(0.5f * (a + g), &sp, &cp);   // ep = cp + i sp
        float sm, cm; __sincosf(0.5f * (a - g), &sm, &cm);   // em = cm + i sm
        sU[tid][0] =  cp * cb;  sU[tid][1] = -sp * cb;       // u00 = conj(ep)*cb
        sU[tid][2] = -cm * sb;  sU[tid][3] =  sm * sb;       // u01 = -conj(em)*sb
        sU[tid][4] =  cm * sb;  sU[tid][5] =  sm * sb;       // u10 = em*sb
        sU[tid][6] =  cp * cb;  sU[tid][7] =  sp * cb;       // u11 = ep*cb
    }
    __syncthreads();

    // Phase B: simulate e_j (j = warp)
    float re[4], im[4];
#pragma unroll
    for (int r = 0; r < 4; r++) { re[r] = 0.f; im[r] = 0.f; }
    if (lane == warp) re[0] = 1.0f;   // m = j < 32 -> r=0, lane=j

    for (int l = 0; l < N_LAYERS; l++) {
#pragma unroll
        for (int q = 0; q < N_QUBITS; q++) {
            const float* U = sU[l * N_QUBITS + q];
            float u00r = U[0], u00i = U[1], u01r = U[2], u01i = U[3];
            float u10r = U[4], u10i = U[5], u11r = U[6], u11i = U[7];
            int p = 6 - q;
            if (p >= 5) {
                int d = 1 << (p - 5);
#pragma unroll
                for (int r0 = 0; r0 < 4; r0++) {
                    if (r0 & d) continue;
                    int r1 = r0 | d;
                    float a0r = re[r0], a0i = im[r0];
                    float a1r = re[r1], a1i = im[r1];
                    re[r0] = u00r*a0r - u00i*a0i + u01r*a1r - u01i*a1i;
                    im[r0] = u00r*a0i + u00i*a0r + u01r*a1i + u01i*a1r;
                    re[r1] = u10r*a0r - u10i*a0i + u11r*a1r - u11i*a1i;
                    im[r1] = u10r*a0i + u10i*a0r + u11r*a1i + u11i*a1r;
                }
            } else {
                int mask = 1 << p;
                int bit = (lane >> p) & 1;
#pragma unroll
                for (int r = 0; r < 4; r++) {
                    float otr = __shfl_xor_sync(0xffffffffu, re[r], mask);
                    float oti = __shfl_xor_sync(0xffffffffu, im[r], mask);
                    float sr = re[r], si = im[r];
                    if (bit == 0) {
                        re[r] = u00r*sr - u00i*si + u01r*otr - u01i*oti;
                        im[r] = u00r*si + u00i*sr + u01r*oti + u01i*otr;
                    } else {
                        re[r] = u10r*otr - u10i*oti + u11r*sr - u11i*si;
                        im[r] = u10r*oti + u10i*otr + u11r*si + u11i*sr;
                    }
                }
            }
        }
        // entangling diagonal: (-1)^C(popc(m),2)
#pragma unroll
        for (int r = 0; r < 4; r++) {
            int m = lane + 32 * r;
            int k = __popc(m);
            if (((k * (k - 1)) >> 1) & 1) { re[r] = -re[r]; im[r] = -im[r]; }
        }
    }

#pragma unroll
    for (int r = 0; r < 4; r++) {
        int m = lane + 32 * r;
        sCr[m * 33 + warp] = re[r];   // lane stride 33 floats -> conflict-free
        sCi[m * 33 + warp] = im[r];
    }
    __syncthreads();

    // Phase C: B element per thread. i = tid>>5 (warp-uniform), j = lane.
    {
        const int i = tid >> 5, j = tid & 31;
        float s = 0.f;
#pragma unroll 4
        for (int m = 0; m < QDIM; m++) {
            float v = sCr[m * 33 + i] * sCr[m * 33 + j]
                    + sCi[m * 33 + i] * sCi[m * 33 + j];
            s += (m < 64) ? v : -v;
        }
        float val = (j < i) ? 0.f : (j == i ? s : 2.f * s);
        g_B[o * N_IN * N_IN + i * N_IN + j] = val;
    }
}

// ---------------------------------------------------------------------------
// Kernel 2: conv. Each thread owns one t, block handles O_PB out-channels.
//   out[b][o][t] = (w^T A_o w)/(w^T w) = (sum_{i<=j} B_ij w_i w_j) / n2
// Symmetric packing: inner j4 loop starts at i>>2 (compile-time after unroll).
// ---------------------------------------------------------------------------
#define TILE_T 128
#define O_PB   2

__global__ __launch_bounds__(TILE_T)
void conv_kernel(const float* __restrict__ x, float* __restrict__ out) {
    __shared__ float sB[O_PB * N_IN * N_IN];          // 8 KB
    __shared__ float xs[IN_CH][TILE_T + KW];

    const int b  = blockIdx.y;
    const int og = blockIdx.z * O_PB;
    const int t0 = blockIdx.x * TILE_T;
    const int tid = threadIdx.x;

    const float* gB = g_B + og * N_IN * N_IN;
    for (int idx = tid; idx < O_PB * N_IN * N_IN; idx += TILE_T)
        sB[idx] = gB[idx];
    for (int idx = tid; idx < IN_CH * (TILE_T + KW); idx += TILE_T) {
        int c = idx / (TILE_T + KW), i = idx % (TILE_T + KW);
        int gi = t0 + i;
        xs[c][i] = (gi < LIN) ? x[(b * IN_CH + c) * LIN + gi] : 0.f;
    }
    __syncthreads();

    const int t = t0 + tid;
    if (t >= LOUT) return;

    float w[N_IN];
    float n2 = 0.f;
#pragma unroll
    for (int c = 0; c < IN_CH; c++)
#pragma unroll
        for (int k = 0; k < KW; k++) {
            float v = xs[c][tid + k];
            w[c * KW + k] = v;
            n2 += v * v;
        }
    const float inv = 1.0f / n2;

#pragma unroll 1
    for (int oo = 0; oo < O_PB; oo++) {
        const float4* Bo = reinterpret_cast<const float4*>(sB + oo * N_IN * N_IN);
        float acc = 0.f;
#pragma unroll
        for (int i = 0; i < N_IN; i++) {
            float s = 0.f;
#pragma unroll
            for (int j4 = (i >> 2); j4 < N_IN / 4; j4++) {   // upper triangle only
                float4 a4 = Bo[i * (N_IN / 4) + j4];
                s += a4.x * w[4*j4+0] + a4.y * w[4*j4+1]
                   + a4.z * w[4*j4+2] + a4.w * w[4*j4+3];
            }
            acc += s * w[i];
        }
        out[(b * OUT_CH + og + oo) * LOUT + t] = acc * inv;
    }
}

// ---------------------------------------------------------------------------
extern "C" void kernel_launch(void* const* d_in, const int* in_sizes, int n_in,
                              void* d_out, int out_size) {
    const float* x      = (const float*)d_in[0];   // (16, 4, 2048) f32
    const float* thetas = (const float*)d_in[1];   // (8, 2, 7, 3) f32
    float* out = (float*)d_out;                    // (16, 8, 2041) f32

    build_kernel<<<OUT_CH, 1024>>>(thetas);
    dim3 grid((LOUT + TILE_T - 1) / TILE_T, BATCH, OUT_CH / O_PB);
    conv_kernel<<<grid, TILE_T>>>(x, out);
}

// round 3
// speedup vs baseline: 2.3363x; 1.3148x over previous
#include <cuda_runtime.h>
#include <cuda_bf16.h>
#include <math.h>

#define IN_CH    4
#define OUT_CH   8
#define KW       8
#define N_LAYERS 2
#define N_IN     32
#define N_QUBITS 7
#define QDIM     128
#define BATCH    16
#define LIN      2048
#define LOUT     (LIN - KW + 1)   // 2041
#define NGATES   (N_LAYERS * N_QUBITS)

// Quadratic-form matrices, symmetric-packed:
//   B[o][i][j] = 0 (j<i), A_ii (j==i), 2*A_ij (j>i)
__device__ float g_B[OUT_CH * N_IN * N_IN];

// ---------------------------------------------------------------------------
// build kernel: grid (4 i-groups, 8 out-ch), block 256 (8 warps).
// Each block re-simulates all 32 basis columns of its out-channel (cheap:
// shared fast-trig gate matrices; each warp simulates 4 columns, 128 amps
// as 4/lane), stores columns to shared, then computes 8 rows of the gram:
//   A_ij = sum_m z0(m) * (Re_i Re_j + Im_i Im_j),  z0 = +1 (m<64), -1 else.
// ---------------------------------------------------------------------------
__global__ __launch_bounds__(256, 1)
void build_kernel(const float* __restrict__ thetas) {
    __shared__ float sU[NGATES][8];
    __shared__ alignas(16) float2 sC[N_IN][QDIM + 2];   // [j][m], row stride 130*8B

    const int ig = blockIdx.x;       // i-group 0..3
    const int o  = blockIdx.y;       // 0..7
    const int tid  = threadIdx.x;
    const int warp = tid >> 5;       // 0..7
    const int lane = tid & 31;

    // Phase A: 14 gate matrices once per block
    if (tid < NGATES) {
        const float* th = thetas + (o * NGATES + tid) * 3;
        float a = th[0], b = th[1], g = th[2];
        float sb, cb; __sincosf(0.5f * b, &sb, &cb);
        float sp, cp; __sincosf(0.5f * (a + g), &sp, &cp);   // ep
        float sm, cm; __sincosf(0.5f * (a - g), &sm, &cm);   // em
        sU[tid][0] =  cp * cb;  sU[tid][1] = -sp * cb;       // u00 = conj(ep)*cb
        sU[tid][2] = -cm * sb;  sU[tid][3] =  sm * sb;       // u01 = -conj(em)*sb
        sU[tid][4] =  cm * sb;  sU[tid][5] =  sm * sb;       // u10 = em*sb
        sU[tid][6] =  cp * cb;  sU[tid][7] =  sp * cb;       // u11 = ep*cb
    }
    __syncthreads();

    // Phase B: warp simulates columns j = 4*warp + c, c in 0..3.
    // Amps: m = lane + 32*r, r in 0..3. Gate q acts on bit p = 6-q.
    float re[4][4], im[4][4];   // [c][r]
#pragma unroll
    for (int c = 0; c < 4; c++)
#pragma unroll
        for (int r = 0; r < 4; r++) { re[c][r] = 0.f; im[c][r] = 0.f; }
#pragma unroll
    for (int c = 0; c < 4; c++)
        if (lane == 4 * warp + c) re[c][0] = 1.0f;   // e_j, j<32 -> r=0

    for (int l = 0; l < N_LAYERS; l++) {
#pragma unroll
        for (int q = 0; q < N_QUBITS; q++) {
            const float* U = sU[l * N_QUBITS + q];
            float u00r = U[0], u00i = U[1], u01r = U[2], u01i = U[3];
            float u10r = U[4], u10i = U[5], u11r = U[6], u11i = U[7];
            int p = 6 - q;
            if (p >= 5) {
                int d = 1 << (p - 5);
#pragma unroll
                for (int c = 0; c < 4; c++)
#pragma unroll
                    for (int r0 = 0; r0 < 4; r0++) {
                        if (r0 & d) continue;
                        int r1 = r0 | d;
                        float a0r = re[c][r0], a0i = im[c][r0];
                        float a1r = re[c][r1], a1i = im[c][r1];
                        re[c][r0] = u00r*a0r - u00i*a0i + u01r*a1r - u01i*a1i;
                        im[c][r0] = u00r*a0i + u00i*a0r + u01r*a1i + u01i*a1r;
                        re[c][r1] = u10r*a0r - u10i*a0i + u11r*a1r - u11i*a1i;
                        im[c][r1] = u10r*a0i + u10i*a0r + u11r*a1i + u11i*a1r;
                    }
            } else {
                int mask = 1 << p;
                int bit = (lane >> p) & 1;
#pragma unroll
                for (int c = 0; c < 4; c++)
#pragma unroll
                    for (int r = 0; r < 4; r++) {
                        float otr = __shfl_xor_sync(0xffffffffu, re[c][r], mask);
                        float oti = __shfl_xor_sync(0xffffffffu, im[c][r], mask);
                        float sr = re[c][r], si = im[c][r];
                        if (bit == 0) {
                            re[c][r] = u00r*sr - u00i*si + u01r*otr - u01i*oti;
                            im[c][r] = u00r*si + u00i*sr + u01r*oti + u01i*otr;
                        } else {
                            re[c][r] = u10r*otr - u10i*oti + u11r*sr - u11i*si;
                            im[c][r] = u10r*oti + u10i*otr + u11r*si + u11i*sr;
                        }
                    }
            }
        }
        // entangling diagonal
#pragma unroll
        for (int r = 0; r < 4; r++) {
            int m = lane + 32 * r;
            int k = __popc(m);
            if (((k * (k - 1)) >> 1) & 1) {
#pragma unroll
                for (int c = 0; c < 4; c++) { re[c][r] = -re[c][r]; im[c][r] = -im[c][r]; }
            }
        }
    }

#pragma unroll
    for (int c = 0; c < 4; c++) {
        int j = 4 * warp + c;
#pragma unroll
        for (int r = 0; r < 4; r++)
            sC[j][lane + 32 * r] = make_float2(re[c][r], im[c][r]);
    }
    __syncthreads();

    // Phase C: warp w computes row i = ig*8 + w, lane = column j.
    {
        const int i = ig * 8 + warp;
        const int j = lane;
        const float2* colI = sC[i];
        const float2* colJ = sC[j];
        float sp_ = 0.f, sn_ = 0.f;
#pragma unroll
        for (int mm = 0; mm < QDIM; mm += 2) {
            float4 a = *reinterpret_cast<const float4*>(colI + mm);  // broadcast
            float4 b = *reinterpret_cast<const float4*>(colJ + mm);
            float v = a.x*b.x + a.y*b.y + a.z*b.z + a.w*b.w;
            if (mm < 64) sp_ += v; else sn_ += v;
        }
        float s = sp_ - sn_;
        float val = (j < i) ? 0.f : (j == i ? s : 2.f * s);
        g_B[(o * N_IN + i) * N_IN + j] = val;
    }
}

// ---------------------------------------------------------------------------
// conv kernel: block 128 threads covers 256 t positions (2 per thread) and
// 2 out-channels. out[b][o][t] = (sum_{i<=j} B_ij w_i w_j) / (w.w)
// ---------------------------------------------------------------------------
#define TILE_T  256
#define NTHR    128
#define O_PB    2

__global__ __launch_bounds__(NTHR)
void conv_kernel(const float* __restrict__ x, float* __restrict__ out) {
    __shared__ alignas(16) float sB[O_PB * N_IN * N_IN];   // 8 KB
    __shared__ float xs[IN_CH][TILE_T + KW];

    const int b  = blockIdx.y;
    const int og = blockIdx.z * O_PB;
    const int t0 = blockIdx.x * TILE_T;
    const int tid = threadIdx.x;

    const float* gB = g_B + og * N_IN * N_IN;
    for (int idx = tid; idx < O_PB * N_IN * N_IN; idx += NTHR)
        sB[idx] = gB[idx];
    for (int idx = tid; idx < IN_CH * (TILE_T + KW); idx += NTHR) {
        int c = idx / (TILE_T + KW), i = idx % (TILE_T + KW);
        int gi = t0 + i;
        xs[c][i] = (gi < LIN) ? x[(b * IN_CH + c) * LIN + gi] : 0.f;
    }
    __syncthreads();

    // two t positions per thread: tid and tid+128
    float w0[N_IN], w1[N_IN];
    float n20 = 0.f, n21 = 0.f;
#pragma unroll
    for (int c = 0; c < IN_CH; c++)
#pragma unroll
        for (int k = 0; k < KW; k++) {
            float v0 = xs[c][tid + k];
            float v1 = xs[c][tid + NTHR + k];
            w0[c * KW + k] = v0;  n20 += v0 * v0;
            w1[c * KW + k] = v1;  n21 += v1 * v1;
        }
    const float inv0 = 1.0f / n20;
    const float inv1 = 1.0f / n21;

    const int t  = t0 + tid;
    const int t2 = t + NTHR;

#pragma unroll 1
    for (int oo = 0; oo < O_PB; oo++) {
        const float4* Bo = reinterpret_cast<const float4*>(sB + oo * N_IN * N_IN);
        float acc0 = 0.f, acc1 = 0.f;
#pragma unroll
        for (int i = 0; i < N_IN; i++) {
            float s0 = 0.f, s1 = 0.f;
#pragma unroll
            for (int j4 = (i >> 2); j4 < N_IN / 4; j4++) {   // upper triangle
                float4 a4 = Bo[i * (N_IN / 4) + j4];
                s0 += a4.x * w0[4*j4+0] + a4.y * w0[4*j4+1]
                    + a4.z * w0[4*j4+2] + a4.w * w0[4*j4+3];
                s1 += a4.x * w1[4*j4+0] + a4.y * w1[4*j4+1]
                    + a4.z * w1[4*j4+2] + a4.w * w1[4*j4+3];
            }
            acc0 += s0 * w0[i];
            acc1 += s1 * w1[i];
        }
        float* po = out + (b * OUT_CH + og + oo) * LOUT;
        if (t  < LOUT) po[t]  = acc0 * inv0;
        if (t2 < LOUT) po[t2] = acc1 * inv1;
    }
}

// ---------------------------------------------------------------------------
extern "C" void kernel_launch(void* const* d_in, const int* in_sizes, int n_in,
                              void* d_out, int out_size) {
    const float* x      = (const float*)d_in[0];   // (16, 4, 2048) f32
    const float* thetas = (const float*)d_in[1];   // (8, 2, 7, 3) f32
    float* out = (float*)d_out;                    // (16, 8, 2041) f32

    dim3 bgrid(4, OUT_CH);                 // 32 blocks
    build_kernel<<<bgrid, 256>>>(thetas);

    dim3 cgrid((LOUT + TILE_T - 1) / TILE_T, BATCH, OUT_CH / O_PB);  // 8x16x4
    conv_kernel<<<cgrid, NTHR>>>(x, out);
}